// round 1
// baseline (speedup 1.0000x reference)
#include <cuda_runtime.h>

// Sepconv: out[b,c,y,x] = sum_{i,j} in[b,c,y*F+i,x*F+j] * V[b,i,y,x] * H[b,j,y,x]
// B=8, C=3, F=5, HO=WO=256. Input: [B,C,HO*F,WO*F] fp32.
// Pure HBM-bound (~185 MB traffic, ~79 MFLOP). One thread per (b,y,x),
// channel loop inside so V/H are loaded once per spatial site.

#define B_ 8
#define C_ 3
#define F_ 5
#define HO_ 256
#define WO_ 256
#define HI_ (HO_ * F_)
#define WI_ (WO_ * F_)

__global__ __launch_bounds__(256) void sepconv_kernel(
    const float* __restrict__ in,
    const float* __restrict__ V,
    const float* __restrict__ H,
    float* __restrict__ out)
{
    int idx = blockIdx.x * blockDim.x + threadIdx.x;  // b*HO*WO + y*WO + x
    if (idx >= B_ * HO_ * WO_) return;

    int x = idx % WO_;
    int y = (idx / WO_) % HO_;
    int b = idx / (WO_ * HO_);

    // Load the 5 vertical + 5 horizontal weights for this (b,y,x) once.
    float v[F_], h[F_];
    int sbase = (b * F_) * (HO_ * WO_) + y * WO_ + x;
#pragma unroll
    for (int i = 0; i < F_; i++) {
        v[i] = V[sbase + i * (HO_ * WO_)];
        h[i] = H[sbase + i * (HO_ * WO_)];
    }

    // Per channel: 5x5 disjoint patch, row-dot with h, then scale by v[i].
#pragma unroll
    for (int c = 0; c < C_; c++) {
        const float* base = in
            + ((long long)((b * C_ + c) * HI_ + y * F_)) * WI_
            + x * F_;
        float acc = 0.0f;
#pragma unroll
        for (int i = 0; i < F_; i++) {
            const float* row = base + i * WI_;
            float rs = 0.0f;
#pragma unroll
            for (int j = 0; j < F_; j++) {
                rs = fmaf(row[j], h[j], rs);
            }
            acc = fmaf(rs, v[i], acc);
        }
        out[((b * C_ + c) * HO_ + y) * WO_ + x] = acc;
    }
}

extern "C" void kernel_launch(void* const* d_in, const int* in_sizes, int n_in,
                              void* d_out, int out_size)
{
    const float* in  = (const float*)d_in[0];  // tensorInput  [8,3,1280,1280]
    const float* V   = (const float*)d_in[1];  // tensorVertical [8,5,256,256]
    const float* H   = (const float*)d_in[2];  // tensorHorizontal [8,5,256,256]
    float* out = (float*)d_out;                // [8,3,256,256]

    const int total = B_ * HO_ * WO_;          // 524288 threads
    const int threads = 256;
    const int blocks = (total + threads - 1) / threads;
    sepconv_kernel<<<blocks, threads>>>(in, V, H, out);
}

// round 2
// speedup vs baseline: 1.0010x; 1.0010x over previous
#include <cuda_runtime.h>

// Sepconv: out[b,c,y,x] = sum_{i,j} in[b,c,5y+i,5x+j] * V[b,i,y,x] * H[b,j,y,x]
// B=8, C=3, F=5, HO=WO=256. Pure HBM-bound (~185 MB).
//
// R2: stage input through shared memory. One block per (b,y) output row.
// Cooperative float4 load of the 5x1280 contiguous input strip (each 128B
// line touched exactly once -> ~5x fewer L1tex wavefronts than the strided
// per-thread patch loads), then stride-5 smem reads (conflict-free, gcd(5,32)=1).

#define B_ 8
#define C_ 3
#define F_ 5
#define HO_ 256
#define WO_ 256
#define HI_ (HO_ * F_)
#define WI_ (WO_ * F_)

#define TILE_FLOATS (F_ * WI_)        // 6400 floats = 25.6 KB
#define TILE_VEC4   (TILE_FLOATS / 4) // 1600 float4

__global__ __launch_bounds__(256) void sepconv_smem_kernel(
    const float* __restrict__ in,
    const float* __restrict__ V,
    const float* __restrict__ H,
    float* __restrict__ out)
{
    __shared__ float s[TILE_FLOATS];

    const int tid = threadIdx.x;           // x = tid (0..255)
    const int y = blockIdx.x % HO_;
    const int b = blockIdx.x / HO_;

    // Per-thread weights for this (b, y, x=tid): coalesced scalar loads.
    float v[F_], h[F_];
    {
        const int sbase = (b * F_) * (HO_ * WO_) + y * WO_ + tid;
#pragma unroll
        for (int i = 0; i < F_; i++) {
            v[i] = V[sbase + i * (HO_ * WO_)];
            h[i] = H[sbase + i * (HO_ * WO_)];
        }
    }

#pragma unroll
    for (int c = 0; c < C_; c++) {
        // --- cooperative load: 5 input rows = 6400 contiguous floats ---
        // Base is 5120B-aligned -> float4-safe.
        const float4* src = reinterpret_cast<const float4*>(
            in + ((long long)((b * C_ + c) * HI_ + y * F_)) * WI_);
        float4* dst = reinterpret_cast<float4*>(s);
#pragma unroll
        for (int k = 0; k < TILE_VEC4 / 256; k++)        // 6 full passes
            dst[tid + k * 256] = src[tid + k * 256];
        {
            int idx = tid + (TILE_VEC4 / 256) * 256;     // remainder 64
            if (idx < TILE_VEC4) dst[idx] = src[idx];
        }
        __syncthreads();

        // --- compute: 5x5 patch at smem offset i*1280 + 5*tid ---
        float acc = 0.0f;
#pragma unroll
        for (int i = 0; i < F_; i++) {
            const float* row = s + i * WI_ + tid * F_;
            float rs = 0.0f;
#pragma unroll
            for (int j = 0; j < F_; j++)
                rs = fmaf(row[j], h[j], rs);
            acc = fmaf(rs, v[i], acc);
        }
        out[((b * C_ + c) * HO_ + y) * WO_ + tid] = acc;

        if (c < C_ - 1) __syncthreads();   // protect smem before next tile
    }
}

extern "C" void kernel_launch(void* const* d_in, const int* in_sizes, int n_in,
                              void* d_out, int out_size)
{
    const float* in  = (const float*)d_in[0];  // [8,3,1280,1280]
    const float* V   = (const float*)d_in[1];  // [8,5,256,256]
    const float* H   = (const float*)d_in[2];  // [8,5,256,256]
    float* out = (float*)d_out;                // [8,3,256,256]

    const int blocks = B_ * HO_;               // 2048 blocks, one per (b,y)
    sepconv_smem_kernel<<<blocks, 256>>>(in, V, H, out);
}